// round 15
// baseline (speedup 1.0000x reference)
#include <cuda_runtime.h>
#include <math.h>

#define INPUT_SIZE 32768
#define FILTER_LEN 8192
#define NUM_CLASSES 512
#define TCLEN 40960      // conv full-length rounded (40959 real outputs, [40959]=0)
#define OUTLEN 65536

// Conv tiling: block computes CT_T outputs as two interleaved f32x2 halves.
#define CT_T 2048
#define CT_HALF 1024
#define CT_KC 256        // filter-chunk per block (32 chunks)
#define CT_KCHUNKS 32
#define CT_THREADS 128
#define NTILES 20        // TCLEN / CT_T
#define NBLK 640         // NTILES * CT_KCHUNKS (all resident: >=5 blocks/SM * 148 = 740)

#define SXP_PHYS 1448    // covers phys(1287); phys(i)=i+(i>>3)
#define MV_HALF 32768    // matvec column split

typedef unsigned long long u64;

static __device__ __align__(16) float g_part[CT_KCHUNKS * TCLEN]; // split-K partials
static __device__ __align__(16) float g_tc[TCLEN];                // current layer conv output
static __device__ __align__(16) float g_out3[OUTLEN];             // final layer full vector
static __device__ float  g_mvp[NUM_CLASSES * 2];   // matvec partials (row, half)
static __device__ double g_n3h[2];                 // ||out3||^2 half partials
static __device__ double g_stt[NBLK], g_stb[NBLK], g_sbb[NBLK];   // per-block slots
static __device__ float  g_ca3, g_cb3;             // layer-3 coefficients (for elem3)
static __device__ unsigned g_barCnt;               // barrier arrivals (self-resetting)
static __device__ unsigned g_barGen;               // barrier generation (monotonic)
static __device__ unsigned g_ctrMv;                // matvec ticket (self-resetting)

// ---- packed f32x2 helpers (Blackwell) ----
static __device__ __forceinline__ u64 pk2(float lo, float hi) {
    u64 r;
    asm("mov.b64 %0, {%1, %2};" : "=l"(r) : "f"(lo), "f"(hi));
    return r;
}
static __device__ __forceinline__ void fma2(u64& d, u64 a, u64 b) {
    asm("fma.rn.f32x2 %0, %1, %2, %0;" : "+l"(d) : "l"(a), "l"(b));
}
static __device__ __forceinline__ void unpk2(u64 v, float& lo, float& hi) {
    asm("mov.b64 {%0, %1}, %2;" : "=f"(lo), "=f"(hi) : "l"(v));
}

// generational grid barrier: all NBLK blocks resident (guaranteed by launch_bounds).
static __device__ __forceinline__ void gbar() {
    __syncthreads();
    if (threadIdx.x == 0) {
        unsigned gen = *((volatile unsigned*)&g_barGen);
        __threadfence();
        unsigned r = atomicAdd(&g_barCnt, 1u);
        if (r == NBLK - 1) {
            g_barCnt = 0;
            __threadfence();
            atomicAdd(&g_barGen, 1u);
        } else {
            while (*((volatile unsigned*)&g_barGen) == gen) __nanosleep(128);
        }
    }
    __syncthreads();
    __threadfence();
}

// scalar coefficients: out = relu(ca*tc + cb*bk)
static __device__ __forceinline__ void compute_coeffs(double Stt, double Stb, double Sbb,
                                                      float* pca, float* pcb) {
    const double C  = 1e-5;
    const double SC = sqrt(C);
    double un = sqrt(Stt); if (un < 1e-15) un = 1e-15;
    double scn = SC * un;
    double gexp = tanh(scn) / scn;            // expmap0 scale
    double nafter = gexp * un;
    double maxnorm = (1.0 - 4e-3) / SC;
    double g = (nafter > maxnorm) ? (maxnorm / un) : gexp;  // proj

    double x2 = g * g * Stt;
    double xy = g * Stb;
    double y2 = Sbb;
    double A  = 1.0 + 2.0 * C * xy + C * y2;
    double B  = 1.0 - C * x2;
    double den = 1.0 + 2.0 * C * xy + C * C * x2 * y2;
    if (den < 1e-15) den = 1e-15;
    *pca = (float)(A * g / den);
    *pcb = (float)(B / den);
}

// Persistent kernel: all 4 conv layers + distributed reduces + coefficients.
// Block b: tile = b>>5, chunk = b&31. 2 grid barriers per layer.
__global__ void __launch_bounds__(CT_THREADS, 5) k_persist(
    const float* __restrict__ hk,
    const float* __restrict__ w0, const float* __restrict__ w1,
    const float* __restrict__ w2, const float* __restrict__ w3,
    const float* __restrict__ b0, const float* __restrict__ b1,
    const float* __restrict__ b2, const float* __restrict__ b3) {

    __shared__ __align__(16) float sw[CT_KC + 16];  // reversed filter chunk + zero pad
    __shared__ u64 sxp[SXP_PHYS];                   // swizzled packed x
    __shared__ float4 red4[CT_THREADS];
    __shared__ double red[CT_THREADS];
    __shared__ float s_coef[2];

    const float* ws[4]  = {w0, w1, w2, w3};
    const float* bks[4] = {b0, b1, b2, b3};
    const int convLens[4] = {40960, 49152, 57344, 65536};

    const int tid    = threadIdx.x;
    const int blk    = blockIdx.x;
    const int tileId = blk >> 5;
    const int chunk  = blk & 31;
    const int jBase  = tileId * CT_T;
    const int k0     = chunk * CT_KC;
    const int lowIdx = jBase - k0 - (CT_KC - 1);
    const int tb     = tid * 8;

    float ca = 0.0f, cb = 0.0f;   // previous layer's coefficients (valid for layer>0)

    for (int layer = 0; layer < 4; layer++) {
        const float* w  = ws[layer];
        const float* bk = bks[layer];
        const float* bkprev = (layer == 0) ? hk : bks[layer - 1];
        const int convLen = convLens[layer];

        float* partBase = &g_part[chunk * TCLEN + jBase];
        const bool skip = (lowIdx >= INPUT_SIZE) || (lowIdx + (CT_HALF + CT_KC + 1022) < 0);

        if (skip) {
            float4 z = make_float4(0.f, 0.f, 0.f, 0.f);
            ((float4*)(partBase + tb))[0] = z;
            ((float4*)(partBase + tb))[1] = z;
            ((float4*)(partBase + CT_HALF + tb))[0] = z;
            ((float4*)(partBase + CT_HALF + tb))[1] = z;
        } else {
            for (int t = tid; t < CT_KC; t += CT_THREADS)
                sw[CT_KC - 1 - t] = w[k0 + t];     // reversed: x-window ascends with tap
            if (tid < 16) sw[CT_KC + tid] = 0.0f;  // pad for last prefetch

            if (layer == 0) {
                for (int i = tid; i < CT_HALF + CT_KC; i += CT_THREADS) {
                    int g0 = lowIdx + i;
                    int g1 = g0 + CT_HALF;
                    float a = (g0 >= 0 && g0 < INPUT_SIZE) ? hk[g0] : 0.0f;
                    float b = (g1 >= 0 && g1 < INPUT_SIZE) ? hk[g1] : 0.0f;
                    sxp[i + (i >> 3)] = pk2(a, b);
                }
            } else {
                for (int i = tid; i < CT_HALF + CT_KC; i += CT_THREADS) {
                    int g0 = lowIdx + i;
                    int g1 = g0 + CT_HALF;
                    float a = 0.0f, b = 0.0f;
                    if (g0 >= 0 && g0 < INPUT_SIZE)
                        a = fmaxf(0.0f, ca * g_tc[g0] + cb * bkprev[g0]);
                    if (g1 >= 0 && g1 < INPUT_SIZE)
                        b = fmaxf(0.0f, ca * g_tc[g1] + cb * bkprev[g1]);
                    sxp[i + (i >> 3)] = pk2(a, b);
                }
            }
            __syncthreads();

            u64 pacc[8];
#pragma unroll
            for (int r = 0; r < 8; r++) pacc[r] = pk2(0.0f, 0.0f);

            u64 xw[16];
            {
                int pb = tb + (tb >> 3);
#pragma unroll
                for (int s = 0; s < 8; s++)  xw[s] = sxp[pb + s];
#pragma unroll
                for (int s = 8; s < 16; s++) xw[s] = sxp[pb + 1 + s];
            }

            const float4* swf4 = (const float4*)sw;
            float4 wA0 = swf4[0], wA1 = swf4[1], wB0 = swf4[2], wB1 = swf4[3];

            for (int kb = 0; kb < CT_KC; kb += 16) {
                const int ni = (kb + 16) >> 2;

                {   // phase A: taps kb..kb+7, operand slot = u + r (<=14)
                    u64 q0 = pk2(wA0.x, wA0.x), q1 = pk2(wA0.y, wA0.y);
                    u64 q2 = pk2(wA0.z, wA0.z), q3 = pk2(wA0.w, wA0.w);
                    u64 q4 = pk2(wA1.x, wA1.x), q5 = pk2(wA1.y, wA1.y);
                    u64 q6 = pk2(wA1.z, wA1.z), q7 = pk2(wA1.w, wA1.w);
#pragma unroll
                    for (int r = 0; r < 8; r++) fma2(pacc[r], q0, xw[r + 0]);
#pragma unroll
                    for (int r = 0; r < 8; r++) fma2(pacc[r], q1, xw[r + 1]);
#pragma unroll
                    for (int r = 0; r < 8; r++) fma2(pacc[r], q2, xw[r + 2]);
#pragma unroll
                    for (int r = 0; r < 8; r++) fma2(pacc[r], q3, xw[r + 3]);
#pragma unroll
                    for (int r = 0; r < 8; r++) fma2(pacc[r], q4, xw[r + 4]);
#pragma unroll
                    for (int r = 0; r < 8; r++) fma2(pacc[r], q5, xw[r + 5]);
#pragma unroll
                    for (int r = 0; r < 8; r++) fma2(pacc[r], q6, xw[r + 6]);
#pragma unroll
                    for (int r = 0; r < 8; r++) fma2(pacc[r], q7, xw[r + 7]);
                }
                float4 nA0 = swf4[ni], nA1 = swf4[ni + 1];
                {
                    int base = tb + kb + 16;
                    int pb = base + (base >> 3);
#pragma unroll
                    for (int s = 0; s < 8; s++) xw[s] = sxp[pb + s];
                }
                {   // phase B: taps kb+8..kb+15, slot = (u + r + 8) & 15
                    u64 q0 = pk2(wB0.x, wB0.x), q1 = pk2(wB0.y, wB0.y);
                    u64 q2 = pk2(wB0.z, wB0.z), q3 = pk2(wB0.w, wB0.w);
                    u64 q4 = pk2(wB1.x, wB1.x), q5 = pk2(wB1.y, wB1.y);
                    u64 q6 = pk2(wB1.z, wB1.z), q7 = pk2(wB1.w, wB1.w);
#pragma unroll
                    for (int r = 0; r < 8; r++) fma2(pacc[r], q0, xw[(r + 8) & 15]);
#pragma unroll
                    for (int r = 0; r < 8; r++) fma2(pacc[r], q1, xw[(r + 9) & 15]);
#pragma unroll
                    for (int r = 0; r < 8; r++) fma2(pacc[r], q2, xw[(r + 10) & 15]);
#pragma unroll
                    for (int r = 0; r < 8; r++) fma2(pacc[r], q3, xw[(r + 11) & 15]);
#pragma unroll
                    for (int r = 0; r < 8; r++) fma2(pacc[r], q4, xw[(r + 12) & 15]);
#pragma unroll
                    for (int r = 0; r < 8; r++) fma2(pacc[r], q5, xw[(r + 13) & 15]);
#pragma unroll
                    for (int r = 0; r < 8; r++) fma2(pacc[r], q6, xw[(r + 14) & 15]);
#pragma unroll
                    for (int r = 0; r < 8; r++) fma2(pacc[r], q7, xw[(r + 15) & 15]);
                }
                float4 nB0 = swf4[ni + 2], nB1 = swf4[ni + 3];
                {
                    int base = tb + kb + 24;
                    int pb = base + (base >> 3);
#pragma unroll
                    for (int s = 0; s < 8; s++) xw[8 + s] = sxp[pb + s];
                }
                wA0 = nA0; wA1 = nA1; wB0 = nB0; wB1 = nB1;
            }

            float lo[8], hi[8];
#pragma unroll
            for (int r = 0; r < 8; r++) unpk2(pacc[r], lo[r], hi[r]);

            ((float4*)(partBase + tb))[0] = make_float4(lo[0], lo[1], lo[2], lo[3]);
            ((float4*)(partBase + tb))[1] = make_float4(lo[4], lo[5], lo[6], lo[7]);
            ((float4*)(partBase + CT_HALF + tb))[0] = make_float4(hi[0], hi[1], hi[2], hi[3]);
            ((float4*)(partBase + CT_HALF + tb))[1] = make_float4(hi[4], hi[5], hi[6], hi[7]);
        }

        gbar();   // all partials visible

        // ---- distributed reduce: block owns 16 float4 columns ----
        // thread: colL = tid&15, grp = tid>>4 sums chunks [grp*4, grp*4+4)
        {
            const int colL = tid & 15;
            const int grp  = tid >> 4;
            const int col  = blk * 16 + colL;          // < 10240
            const float4* gp = (const float4*)g_part;
            const int st = TCLEN / 4;
            float4 s = gp[(grp * 4) * st + col];
#pragma unroll
            for (int c = 1; c < 4; c++) {
                float4 v = gp[(grp * 4 + c) * st + col];
                s.x += v.x; s.y += v.y; s.z += v.z; s.w += v.w;
            }
            red4[tid] = s;
            __syncthreads();
            for (int off = 64; off >= 16; off >>= 1) {
                if (tid < off) {
                    float4 v = red4[tid + off];
                    red4[tid].x += v.x; red4[tid].y += v.y;
                    red4[tid].z += v.z; red4[tid].w += v.w;
                }
                __syncthreads();
            }
            float stt = 0.0f, stb = 0.0f, sbb = 0.0f;
            if (tid < 16) {
                float4 sv = red4[tid];
                ((float4*)g_tc)[col] = sv;
                float4 bb = ((const float4*)bk)[col];
                stt = fmaf(sv.x, sv.x, fmaf(sv.y, sv.y, fmaf(sv.z, sv.z, sv.w * sv.w)));
                stb = fmaf(sv.x, bb.x, fmaf(sv.y, bb.y, fmaf(sv.z, bb.z, sv.w * bb.w)));
                sbb = fmaf(bb.x, bb.x, fmaf(bb.y, bb.y, fmaf(bb.z, bb.z, bb.w * bb.w)));
            }
            // Sbb tail beyond TCLEN (tc is structurally zero there)
            {
                int g = blk * CT_THREADS + tid;
                for (int i = TCLEN / 4 + g; i < convLen / 4; i += NBLK * CT_THREADS) {
                    float4 bb = ((const float4*)bk)[i];
                    sbb = fmaf(bb.x, bb.x, fmaf(bb.y, bb.y,
                          fmaf(bb.z, bb.z, fmaf(bb.w, bb.w, sbb))));
                }
            }
            __syncthreads();
            red[tid] = (double)stt; __syncthreads();
            for (int s2 = 64; s2 > 0; s2 >>= 1) {
                if (tid < s2) red[tid] += red[tid + s2];
                __syncthreads();
            }
            if (tid == 0) g_stt[blk] = red[0];
            __syncthreads();
            red[tid] = (double)stb; __syncthreads();
            for (int s2 = 64; s2 > 0; s2 >>= 1) {
                if (tid < s2) red[tid] += red[tid + s2];
                __syncthreads();
            }
            if (tid == 0) g_stb[blk] = red[0];
            __syncthreads();
            red[tid] = (double)sbb; __syncthreads();
            for (int s2 = 64; s2 > 0; s2 >>= 1) {
                if (tid < s2) red[tid] += red[tid + s2];
                __syncthreads();
            }
            if (tid == 0) g_sbb[blk] = red[0];
        }

        gbar();   // all slots visible

        // ---- every block computes coefficients redundantly (deterministic order) ----
        {
            double a0 = 0.0, a1 = 0.0, a2 = 0.0;
            for (int i = tid; i < NBLK; i += CT_THREADS) {
                a0 += g_stt[i]; a1 += g_stb[i]; a2 += g_sbb[i];
            }
            red[tid] = a0; __syncthreads();
            for (int s2 = 64; s2 > 0; s2 >>= 1) {
                if (tid < s2) red[tid] += red[tid + s2];
                __syncthreads();
            }
            double Stt = red[0]; __syncthreads();
            red[tid] = a1; __syncthreads();
            for (int s2 = 64; s2 > 0; s2 >>= 1) {
                if (tid < s2) red[tid] += red[tid + s2];
                __syncthreads();
            }
            double Stb = red[0]; __syncthreads();
            red[tid] = a2; __syncthreads();
            for (int s2 = 64; s2 > 0; s2 >>= 1) {
                if (tid < s2) red[tid] += red[tid + s2];
                __syncthreads();
            }
            double Sbb = red[0];
            if (tid == 0) {
                float nca, ncb;
                compute_coeffs(Stt, Stb, Sbb, &nca, &ncb);
                s_coef[0] = nca; s_coef[1] = ncb;
            }
            __syncthreads();
            ca = s_coef[0];
            cb = s_coef[1];
        }
    }

    if (blk == 0 && tid == 0) { g_ca3 = ca; g_cb3 = cb; }
}

// layer 3 tail: full 65536 output (pure elementwise; norm folded into matvec).
__global__ void __launch_bounds__(256) k_elem3(const float* __restrict__ bk) {
    const float ca = g_ca3, cb = g_cb3;
    const int idx = blockIdx.x * 256 + threadIdx.x;  // float4 index
    float4 tc = make_float4(0.f, 0.f, 0.f, 0.f);
    if (idx < TCLEN / 4) tc = ((const float4*)g_tc)[idx];
    float4 b = ((const float4*)bk)[idx];
    float4 v;
    v.x = fmaxf(0.0f, ca * tc.x + cb * b.x);
    v.y = fmaxf(0.0f, ca * tc.y + cb * b.y);
    v.z = fmaxf(0.0f, ca * tc.z + cb * b.z);
    v.w = fmaxf(0.0f, ca * tc.w + cb * b.w);
    ((float4*)g_out3)[idx] = v;
}

// Matvec split by (row, half); row-0 blocks accumulate ||out3-half||^2.
// Ticket winner combines halves + logmap0/euc_to_hyp/softmax.
__global__ void __launch_bounds__(256) k_matvec(const float* __restrict__ trans,
                                                float* __restrict__ out) {
    __shared__ float sh[256];
    __shared__ double shd[256];
    const int t = threadIdx.x;
    const int row = blockIdx.x;
    const int half = blockIdx.y;
    const float4* tr = (const float4*)(trans + (size_t)row * OUTLEN + half * MV_HALF);
    const float4* ov = (const float4*)(g_out3 + half * MV_HALF);

    float acc[8];
#pragma unroll
    for (int i = 0; i < 8; i++) acc[i] = 0.0f;
    float n2 = 0.0f;
    const bool wantN = (row == 0);

    for (int i = t; i < MV_HALF / 8; i += 256) {
        float4 t0 = __ldcs(&tr[2 * i]), t1 = __ldcs(&tr[2 * i + 1]);
        float4 o0 = ov[2 * i], o1 = ov[2 * i + 1];
        acc[0] = fmaf(t0.x, o0.x, acc[0]);
        acc[1] = fmaf(t0.y, o0.y, acc[1]);
        acc[2] = fmaf(t0.z, o0.z, acc[2]);
        acc[3] = fmaf(t0.w, o0.w, acc[3]);
        acc[4] = fmaf(t1.x, o1.x, acc[4]);
        acc[5] = fmaf(t1.y, o1.y, acc[5]);
        acc[6] = fmaf(t1.z, o1.z, acc[6]);
        acc[7] = fmaf(t1.w, o1.w, acc[7]);
        if (wantN) {
            n2 = fmaf(o0.x, o0.x, fmaf(o0.y, o0.y, fmaf(o0.z, o0.z, fmaf(o0.w, o0.w,
                 fmaf(o1.x, o1.x, fmaf(o1.y, o1.y, fmaf(o1.z, o1.z, fmaf(o1.w, o1.w, n2))))))));
        }
    }
    float a = ((acc[0] + acc[1]) + (acc[2] + acc[3]))
            + ((acc[4] + acc[5]) + (acc[6] + acc[7]));
    sh[t] = a; __syncthreads();
    for (int s = 128; s > 0; s >>= 1) {
        if (t < s) sh[t] += sh[t + s];
        __syncthreads();
    }
    if (wantN) {
        shd[t] = (double)n2; __syncthreads();
        for (int s = 128; s > 0; s >>= 1) {
            if (t < s) shd[t] += shd[t + s];
            __syncthreads();
        }
        if (t == 0) g_n3h[half] = shd[0];
    }

    __shared__ int s_last;
    if (t == 0) {
        g_mvp[row * 2 + half] = sh[0];
        __threadfence();
        unsigned r = atomicAdd(&g_ctrMv, 1u);
        s_last = (r == gridDim.x * gridDim.y - 1) ? 1 : 0;
        if (s_last) g_ctrMv = 0;   // reset for next replay
    }
    __syncthreads();
    if (!s_last) return;
    __threadfence();

    const double C  = 1e-5;
    const double SC = sqrt(C);
    double pn2 = g_n3h[0] + g_n3h[1];
    double pn = sqrt(pn2); if (pn < 1e-15) pn = 1e-15;
    double z = SC * pn;
    if (z > 1.0 - 1e-7) z = 1.0 - 1e-7;
    double slog = atanh(z) / (SC * pn);
    double maxnorm = (1.0 - 4e-3) / SC;

    double val[2];
#pragma unroll
    for (int q = 0; q < 2; q++) {
        int r = t + 256 * q;
        double logit = (double)g_mvp[r * 2 + 0] + (double)g_mvp[r * 2 + 1];
        double l = slog * logit;
        double un = fabs(l); if (un < 1e-15) un = 1e-15;
        double scn = SC * un;
        double v = tanh(scn) / scn * l;
        double av = fabs(v); if (av < 1e-15) av = 1e-15;
        if (av > maxnorm) v = v / av * maxnorm;
        val[q] = v;
    }
    __shared__ double sd[256];
    sd[t] = fmax(val[0], val[1]); __syncthreads();
    for (int s = 128; s > 0; s >>= 1) {
        if (t < s) sd[t] = fmax(sd[t], sd[t + s]);
        __syncthreads();
    }
    double m = sd[0];
    __syncthreads();
    double e0 = exp(val[0] - m), e1 = exp(val[1] - m);
    sd[t] = e0 + e1; __syncthreads();
    for (int s = 128; s > 0; s >>= 1) {
        if (t < s) sd[t] += sd[t + s];
        __syncthreads();
    }
    double inv = 1.0 / sd[0];
    out[t]       = (float)(e0 * inv);
    out[t + 256] = (float)(e1 * inv);
}

extern "C" void kernel_launch(void* const* d_in, const int* in_sizes, int n_in,
                              void* d_out, int out_size) {
    const float* hk = nullptr;
    const float* w[4]   = {nullptr, nullptr, nullptr, nullptr};
    const float* bkk[4] = {nullptr, nullptr, nullptr, nullptr};
    const float* trans = nullptr;
    int wi = 0;
    for (int i = 0; i < n_in; i++) {
        int s = in_sizes[i];
        const float* p = (const float*)d_in[i];
        if      (s == INPUT_SIZE) hk = p;
        else if (s == FILTER_LEN) { if (wi < 4) w[wi++] = p; }
        else if (s == 40960) bkk[0] = p;
        else if (s == 49152) bkk[1] = p;
        else if (s == 57344) bkk[2] = p;
        else if (s == 65536) bkk[3] = p;
        else if (s == NUM_CLASSES * OUTLEN) trans = p;
    }

    k_persist<<<NBLK, CT_THREADS>>>(hk, w[0], w[1], w[2], w[3],
                                    bkk[0], bkk[1], bkk[2], bkk[3]);
    k_elem3<<<OUTLEN / 1024, 256>>>(bkk[3]);
    k_matvec<<<dim3(NUM_CLASSES, 2), 256>>>(trans, (float*)d_out);
}

// round 16
// speedup vs baseline: 1.0211x; 1.0211x over previous
#include <cuda_runtime.h>
#include <math.h>

#define INPUT_SIZE 32768
#define FILTER_LEN 8192
#define NUM_CLASSES 512
#define TCLEN 40960      // conv full-length rounded (40959 real outputs, [40959]=0)
#define OUTLEN 65536

// Conv tiling: block computes CT_T outputs as two interleaved f32x2 halves.
#define CT_T 2048
#define CT_HALF 1024
#define CT_KC 256        // filter-chunk per block (32 chunks -> 640 blocks)
#define CT_KCHUNKS 32
#define CT_THREADS 128   // each thread: 8 low + 8 high outputs
#define NTILES 20        // TCLEN / CT_T

#define SXP_PHYS 1448    // covers phys(1287); phys(i)=i+(i>>3)
#define NRM_BLOCKS 40
#define NRM_THREADS 256  // 40*256 = 10240 = TCLEN/4 columns

#define MV_HALF 32768    // matvec column split

typedef unsigned long long u64;

static __device__ __align__(16) float g_tcBuf[2][TCLEN];  // double-buffered conv outputs
static __device__ __align__(16) float g_out3[OUTLEN];     // final layer full vector
static __device__ float  g_mvp[NUM_CLASSES * 2];   // matvec partials (row, half)
static __device__ double g_n3h[2];                 // ||out3||^2 half partials
static __device__ double g_stt[NRM_BLOCKS], g_stb[NRM_BLOCKS], g_sbb[NRM_BLOCKS];
static __device__ float  g_ca[4], g_cb[4];   // per-layer mobius coefficients
static __device__ unsigned g_ctrR[4];        // norm tickets (self-resetting)
static __device__ unsigned g_ctrMv;          // matvec ticket (self-resetting)

// ---- packed f32x2 helpers (Blackwell) ----
static __device__ __forceinline__ u64 pk2(float lo, float hi) {
    u64 r;
    asm("mov.b64 %0, {%1, %2};" : "=l"(r) : "f"(lo), "f"(hi));
    return r;
}
static __device__ __forceinline__ void fma2(u64& d, u64 a, u64 b) {
    asm("fma.rn.f32x2 %0, %1, %2, %0;" : "+l"(d) : "l"(a), "l"(b));
}
static __device__ __forceinline__ void unpk2(u64 v, float& lo, float& hi) {
    asm("mov.b64 {%0, %1}, %2;" : "=f"(lo), "=f"(hi) : "l"(v));
}

// zero layer-0 tc buffer (once per replay)
__global__ void __launch_bounds__(256) k_zero() {
    ((float4*)g_tcBuf[0])[blockIdx.x * 256 + threadIdx.x] =
        make_float4(0.f, 0.f, 0.f, 0.f);
}

// scalar coefficients: out = relu(ca*tc + cb*bk)
static __device__ __forceinline__ void compute_coeffs(double Stt, double Stb, double Sbb,
                                                      float* pca, float* pcb) {
    const double C  = 1e-5;
    const double SC = sqrt(C);
    double un = sqrt(Stt); if (un < 1e-15) un = 1e-15;
    double scn = SC * un;
    double gexp = tanh(scn) / scn;            // expmap0 scale
    double nafter = gexp * un;
    double maxnorm = (1.0 - 4e-3) / SC;
    double g = (nafter > maxnorm) ? (maxnorm / un) : gexp;  // proj

    double x2 = g * g * Stt;
    double xy = g * Stb;
    double y2 = Sbb;
    double A  = 1.0 + 2.0 * C * xy + C * y2;
    double B  = 1.0 - C * x2;
    double den = 1.0 + 2.0 * C * xy + C * C * x2 * y2;
    if (den < 1e-15) den = 1e-15;
    *pca = (float)(A * g / den);
    *pcb = (float)(B / den);
}

// tc[j] = sum_k w[k] * x[j-k]; x for layer>0 generated inline:
//   x[gi] = relu(ca*tcPrev[gi] + cb*bkprev[gi])
// f32x2 lanes = (output j, output j+1024). Weights software-pipelined.
// Epilogue: atomicAdd (REDG) of the 16 per-thread outputs into tcCur —
// no split-K partial buffer, no second gather pass.
__global__ void __launch_bounds__(CT_THREADS) k_conv(const float* __restrict__ xin,
                                                     const float* __restrict__ w,
                                                     const float* __restrict__ bkprev,
                                                     const float* __restrict__ tcPrev,
                                                     float* __restrict__ tcCur,
                                                     int layer) {
    __shared__ __align__(16) float sw[CT_KC + 16];  // reversed filter chunk + zero pad
    __shared__ u64 sxp[SXP_PHYS];                   // swizzled packed x

    const int tid    = threadIdx.x;
    const int jBase  = blockIdx.x * CT_T;
    const int k0     = blockIdx.y * CT_KC;
    const int lowIdx = jBase - k0 - (CT_KC - 1);
    const int tb     = tid * 8;

    // entire x-window (both lanes) outside [0, INPUT_SIZE) -> no contribution
    if (lowIdx >= INPUT_SIZE || lowIdx + (CT_HALF + CT_KC + 1022) < 0) return;

    for (int t = tid; t < CT_KC; t += CT_THREADS)
        sw[CT_KC - 1 - t] = w[k0 + t];     // reversed so x-window ascends with tap
    if (tid < 16) sw[CT_KC + tid] = 0.0f;  // pad for last prefetch

    if (layer == 0) {
        for (int i = tid; i < CT_HALF + CT_KC; i += CT_THREADS) {
            int g0 = lowIdx + i;
            int g1 = g0 + CT_HALF;
            float a = (g0 >= 0 && g0 < INPUT_SIZE) ? xin[g0] : 0.0f;
            float b = (g1 >= 0 && g1 < INPUT_SIZE) ? xin[g1] : 0.0f;
            sxp[i + (i >> 3)] = pk2(a, b);
        }
    } else {
        const float ca = g_ca[layer - 1], cb = g_cb[layer - 1];
        for (int i = tid; i < CT_HALF + CT_KC; i += CT_THREADS) {
            int g0 = lowIdx + i;
            int g1 = g0 + CT_HALF;
            float a = 0.0f, b = 0.0f;
            if (g0 >= 0 && g0 < INPUT_SIZE)
                a = fmaxf(0.0f, ca * tcPrev[g0] + cb * bkprev[g0]);
            if (g1 >= 0 && g1 < INPUT_SIZE)
                b = fmaxf(0.0f, ca * tcPrev[g1] + cb * bkprev[g1]);
            sxp[i + (i >> 3)] = pk2(a, b);
        }
    }
    __syncthreads();

    u64 pacc[8];
#pragma unroll
    for (int r = 0; r < 8; r++) pacc[r] = pk2(0.0f, 0.0f);

    // circular 16-slot window: slot s <-> logical tb + kb + s at phase-A entry
    u64 xw[16];
    {
        int pb = tb + (tb >> 3);
#pragma unroll
        for (int s = 0; s < 8; s++)  xw[s] = sxp[pb + s];
#pragma unroll
        for (int s = 8; s < 16; s++) xw[s] = sxp[pb + 1 + s];
    }

    const float4* swf4 = (const float4*)sw;
    float4 wA0 = swf4[0], wA1 = swf4[1], wB0 = swf4[2], wB1 = swf4[3];

    for (int kb = 0; kb < CT_KC; kb += 16) {
        const int ni = (kb + 16) >> 2;     // next iteration's float4 base (pad-safe)

        {   // phase A: taps kb..kb+7, operand slot = u + r (<=14)
            u64 q0 = pk2(wA0.x, wA0.x), q1 = pk2(wA0.y, wA0.y);
            u64 q2 = pk2(wA0.z, wA0.z), q3 = pk2(wA0.w, wA0.w);
            u64 q4 = pk2(wA1.x, wA1.x), q5 = pk2(wA1.y, wA1.y);
            u64 q6 = pk2(wA1.z, wA1.z), q7 = pk2(wA1.w, wA1.w);
#pragma unroll
            for (int r = 0; r < 8; r++) fma2(pacc[r], q0, xw[r + 0]);
#pragma unroll
            for (int r = 0; r < 8; r++) fma2(pacc[r], q1, xw[r + 1]);
#pragma unroll
            for (int r = 0; r < 8; r++) fma2(pacc[r], q2, xw[r + 2]);
#pragma unroll
            for (int r = 0; r < 8; r++) fma2(pacc[r], q3, xw[r + 3]);
#pragma unroll
            for (int r = 0; r < 8; r++) fma2(pacc[r], q4, xw[r + 4]);
#pragma unroll
            for (int r = 0; r < 8; r++) fma2(pacc[r], q5, xw[r + 5]);
#pragma unroll
            for (int r = 0; r < 8; r++) fma2(pacc[r], q6, xw[r + 6]);
#pragma unroll
            for (int r = 0; r < 8; r++) fma2(pacc[r], q7, xw[r + 7]);
        }
        float4 nA0 = swf4[ni], nA1 = swf4[ni + 1];
        {   // refill slots 0..7 <- logical tb+kb+16..+23
            int base = tb + kb + 16;
            int pb = base + (base >> 3);
#pragma unroll
            for (int s = 0; s < 8; s++) xw[s] = sxp[pb + s];
        }
        {   // phase B: taps kb+8..kb+15, operand slot = (u + r + 8) & 15
            u64 q0 = pk2(wB0.x, wB0.x), q1 = pk2(wB0.y, wB0.y);
            u64 q2 = pk2(wB0.z, wB0.z), q3 = pk2(wB0.w, wB0.w);
            u64 q4 = pk2(wB1.x, wB1.x), q5 = pk2(wB1.y, wB1.y);
            u64 q6 = pk2(wB1.z, wB1.z), q7 = pk2(wB1.w, wB1.w);
#pragma unroll
            for (int r = 0; r < 8; r++) fma2(pacc[r], q0, xw[(r + 8) & 15]);
#pragma unroll
            for (int r = 0; r < 8; r++) fma2(pacc[r], q1, xw[(r + 9) & 15]);
#pragma unroll
            for (int r = 0; r < 8; r++) fma2(pacc[r], q2, xw[(r + 10) & 15]);
#pragma unroll
            for (int r = 0; r < 8; r++) fma2(pacc[r], q3, xw[(r + 11) & 15]);
#pragma unroll
            for (int r = 0; r < 8; r++) fma2(pacc[r], q4, xw[(r + 12) & 15]);
#pragma unroll
            for (int r = 0; r < 8; r++) fma2(pacc[r], q5, xw[(r + 13) & 15]);
#pragma unroll
            for (int r = 0; r < 8; r++) fma2(pacc[r], q6, xw[(r + 14) & 15]);
#pragma unroll
            for (int r = 0; r < 8; r++) fma2(pacc[r], q7, xw[(r + 15) & 15]);
        }
        float4 nB0 = swf4[ni + 2], nB1 = swf4[ni + 3];
        {   // refill slots 8..15 <- logical tb+kb+24..+31 (last iter junk, unused)
            int base = tb + kb + 24;
            int pb = base + (base >> 3);
#pragma unroll
            for (int s = 0; s < 8; s++) xw[8 + s] = sxp[pb + s];
        }
        wA0 = nA0; wA1 = nA1; wB0 = nB0; wB1 = nB1;
    }

    float lo[8], hi[8];
#pragma unroll
    for (int r = 0; r < 8; r++) unpk2(pacc[r], lo[r], hi[r]);

    float* dstL = tcCur + jBase + tb;
    float* dstH = tcCur + jBase + CT_HALF + tb;
#pragma unroll
    for (int r = 0; r < 8; r++) atomicAdd(dstL + r, lo[r]);
#pragma unroll
    for (int r = 0; r < 8; r++) atomicAdd(dstH + r, hi[r]);
}

// Per-layer norm pass: read tcCur once, accumulate Stt/Stb/Sbb, zero tcNext for
// the following layer, ticket winner computes coefficients. 40x256 = 10240 thr.
__global__ void __launch_bounds__(NRM_THREADS) k_norm(const float* __restrict__ bk,
                                                      const float* __restrict__ tcCur,
                                                      float* __restrict__ tcNext,
                                                      int convLen, int slot) {
    __shared__ double sh[NRM_THREADS];
    __shared__ unsigned s_rank;
    const int t = threadIdx.x;
    const int idx = blockIdx.x * NRM_THREADS + t;   // float4 index, < 10240
    float stt, stb, sbb;

    {
        float4 s = ((const float4*)tcCur)[idx];
        float4 b = ((const float4*)bk)[idx];
        stt = fmaf(s.x, s.x, fmaf(s.y, s.y, fmaf(s.z, s.z, s.w * s.w)));
        stb = fmaf(s.x, b.x, fmaf(s.y, b.y, fmaf(s.z, b.z, s.w * b.w)));
        sbb = fmaf(b.x, b.x, fmaf(b.y, b.y, fmaf(b.z, b.z, b.w * b.w)));
        if (tcNext) ((float4*)tcNext)[idx] = make_float4(0.f, 0.f, 0.f, 0.f);
    }
    // tail of Sbb beyond TCLEN (tc is structurally zero there)
    for (int i = idx + TCLEN / 4; i < convLen / 4; i += NRM_BLOCKS * NRM_THREADS) {
        float4 b = ((const float4*)bk)[i];
        sbb = fmaf(b.x, b.x, fmaf(b.y, b.y, fmaf(b.z, b.z, fmaf(b.w, b.w, sbb))));
    }

    sh[t] = (double)stt; __syncthreads();
    for (int s = 128; s > 0; s >>= 1) { if (t < s) sh[t] += sh[t + s]; __syncthreads(); }
    if (t == 0) g_stt[blockIdx.x] = sh[0];
    __syncthreads();
    sh[t] = (double)stb; __syncthreads();
    for (int s = 128; s > 0; s >>= 1) { if (t < s) sh[t] += sh[t + s]; __syncthreads(); }
    if (t == 0) g_stb[blockIdx.x] = sh[0];
    __syncthreads();
    sh[t] = (double)sbb; __syncthreads();
    for (int s = 128; s > 0; s >>= 1) { if (t < s) sh[t] += sh[t + s]; __syncthreads(); }
    if (t == 0) {
        g_sbb[blockIdx.x] = sh[0];
        __threadfence();
        s_rank = atomicAdd(&g_ctrR[slot], 1u);
    }
    __syncthreads();
    if (t == 0 && s_rank == gridDim.x - 1) {
        g_ctrR[slot] = 0;           // reset for next graph replay
        __threadfence();
        double Stt = 0.0, Stb = 0.0, Sbb = 0.0;
        for (int i = 0; i < NRM_BLOCKS; i++) {
            Stt += g_stt[i]; Stb += g_stb[i]; Sbb += g_sbb[i];
        }
        float ca, cb;
        compute_coeffs(Stt, Stb, Sbb, &ca, &cb);
        g_ca[slot] = ca;
        g_cb[slot] = cb;
    }
}

// layer 3 tail: full 65536 output (pure elementwise; norm folded into matvec).
__global__ void __launch_bounds__(256) k_elem3(const float* __restrict__ bk,
                                               const float* __restrict__ tc3) {
    const float ca = g_ca[3], cb = g_cb[3];
    const int idx = blockIdx.x * 256 + threadIdx.x;  // float4 index
    float4 tc = make_float4(0.f, 0.f, 0.f, 0.f);
    if (idx < TCLEN / 4) tc = ((const float4*)tc3)[idx];
    float4 b = ((const float4*)bk)[idx];
    float4 v;
    v.x = fmaxf(0.0f, ca * tc.x + cb * b.x);
    v.y = fmaxf(0.0f, ca * tc.y + cb * b.y);
    v.z = fmaxf(0.0f, ca * tc.z + cb * b.z);
    v.w = fmaxf(0.0f, ca * tc.w + cb * b.w);
    ((float4*)g_out3)[idx] = v;
}

// Matvec split by (row, half); row-0 blocks accumulate ||out3-half||^2.
// Ticket winner combines halves + logmap0/euc_to_hyp/softmax.
__global__ void __launch_bounds__(256) k_matvec(const float* __restrict__ trans,
                                                float* __restrict__ out) {
    __shared__ float sh[256];
    __shared__ double shd[256];
    const int t = threadIdx.x;
    const int row = blockIdx.x;
    const int half = blockIdx.y;
    const float4* tr = (const float4*)(trans + (size_t)row * OUTLEN + half * MV_HALF);
    const float4* ov = (const float4*)(g_out3 + half * MV_HALF);

    float acc[8];
#pragma unroll
    for (int i = 0; i < 8; i++) acc[i] = 0.0f;
    float n2 = 0.0f;
    const bool wantN = (row == 0);

    for (int i = t; i < MV_HALF / 8; i += 256) {
        float4 t0 = __ldcs(&tr[2 * i]), t1 = __ldcs(&tr[2 * i + 1]);
        float4 o0 = ov[2 * i], o1 = ov[2 * i + 1];
        acc[0] = fmaf(t0.x, o0.x, acc[0]);
        acc[1] = fmaf(t0.y, o0.y, acc[1]);
        acc[2] = fmaf(t0.z, o0.z, acc[2]);
        acc[3] = fmaf(t0.w, o0.w, acc[3]);
        acc[4] = fmaf(t1.x, o1.x, acc[4]);
        acc[5] = fmaf(t1.y, o1.y, acc[5]);
        acc[6] = fmaf(t1.z, o1.z, acc[6]);
        acc[7] = fmaf(t1.w, o1.w, acc[7]);
        if (wantN) {
            n2 = fmaf(o0.x, o0.x, fmaf(o0.y, o0.y, fmaf(o0.z, o0.z, fmaf(o0.w, o0.w,
                 fmaf(o1.x, o1.x, fmaf(o1.y, o1.y, fmaf(o1.z, o1.z, fmaf(o1.w, o1.w, n2))))))));
        }
    }
    float a = ((acc[0] + acc[1]) + (acc[2] + acc[3]))
            + ((acc[4] + acc[5]) + (acc[6] + acc[7]));
    sh[t] = a; __syncthreads();
    for (int s = 128; s > 0; s >>= 1) {
        if (t < s) sh[t] += sh[t + s];
        __syncthreads();
    }
    if (wantN) {
        shd[t] = (double)n2; __syncthreads();
        for (int s = 128; s > 0; s >>= 1) {
            if (t < s) shd[t] += shd[t + s];
            __syncthreads();
        }
        if (t == 0) g_n3h[half] = shd[0];
    }

    __shared__ int s_last;
    if (t == 0) {
        g_mvp[row * 2 + half] = sh[0];
        __threadfence();
        unsigned r = atomicAdd(&g_ctrMv, 1u);
        s_last = (r == gridDim.x * gridDim.y - 1) ? 1 : 0;
        if (s_last) g_ctrMv = 0;   // reset for next replay
    }
    __syncthreads();
    if (!s_last) return;
    __threadfence();

    const double C  = 1e-5;
    const double SC = sqrt(C);
    double pn2 = g_n3h[0] + g_n3h[1];
    double pn = sqrt(pn2); if (pn < 1e-15) pn = 1e-15;
    double z = SC * pn;
    if (z > 1.0 - 1e-7) z = 1.0 - 1e-7;
    double slog = atanh(z) / (SC * pn);
    double maxnorm = (1.0 - 4e-3) / SC;

    double val[2];
#pragma unroll
    for (int q = 0; q < 2; q++) {
        int r = t + 256 * q;
        double logit = (double)g_mvp[r * 2 + 0] + (double)g_mvp[r * 2 + 1];
        double l = slog * logit;
        double un = fabs(l); if (un < 1e-15) un = 1e-15;
        double scn = SC * un;
        double v = tanh(scn) / scn * l;
        double av = fabs(v); if (av < 1e-15) av = 1e-15;
        if (av > maxnorm) v = v / av * maxnorm;
        val[q] = v;
    }
    __shared__ double sd[256];
    sd[t] = fmax(val[0], val[1]); __syncthreads();
    for (int s = 128; s > 0; s >>= 1) {
        if (t < s) sd[t] = fmax(sd[t], sd[t + s]);
        __syncthreads();
    }
    double m = sd[0];
    __syncthreads();
    double e0 = exp(val[0] - m), e1 = exp(val[1] - m);
    sd[t] = e0 + e1; __syncthreads();
    for (int s = 128; s > 0; s >>= 1) {
        if (t < s) sd[t] += sd[t + s];
        __syncthreads();
    }
    double inv = 1.0 / sd[0];
    out[t]       = (float)(e0 * inv);
    out[t + 256] = (float)(e1 * inv);
}

extern "C" void kernel_launch(void* const* d_in, const int* in_sizes, int n_in,
                              void* d_out, int out_size) {
    const float* hk = nullptr;
    const float* w[4]   = {nullptr, nullptr, nullptr, nullptr};
    const float* bkk[4] = {nullptr, nullptr, nullptr, nullptr};
    const float* trans = nullptr;
    int wi = 0;
    for (int i = 0; i < n_in; i++) {
        int s = in_sizes[i];
        const float* p = (const float*)d_in[i];
        if      (s == INPUT_SIZE) hk = p;
        else if (s == FILTER_LEN) { if (wi < 4) w[wi++] = p; }
        else if (s == 40960) bkk[0] = p;
        else if (s == 49152) bkk[1] = p;
        else if (s == 57344) bkk[2] = p;
        else if (s == 65536) bkk[3] = p;
        else if (s == NUM_CLASSES * OUTLEN) trans = p;
    }

    const int convLens[4] = {40960, 49152, 57344, 65536};

    float* tcBase = nullptr;
    cudaGetSymbolAddress((void**)&tcBase, g_tcBuf);
    float* tcb[2] = {tcBase, tcBase + TCLEN};

    k_zero<<<NRM_BLOCKS, NRM_THREADS>>>();   // zero buffer 0 for layer 0
    for (int i = 0; i < 4; i++) {
        const float* bkprev = (i == 0) ? nullptr : bkk[i - 1];
        const float* tcPrev = (i == 0) ? nullptr : tcb[(i - 1) & 1];
        float* tcCur  = tcb[i & 1];
        float* tcNext = (i < 3) ? tcb[(i + 1) & 1] : nullptr;
        k_conv<<<dim3(NTILES, CT_KCHUNKS), CT_THREADS>>>(hk, w[i], bkprev,
                                                         tcPrev, tcCur, i);
        k_norm<<<NRM_BLOCKS, NRM_THREADS>>>(bkk[i], tcCur, tcNext, convLens[i], i);
    }
    k_elem3<<<OUTLEN / 1024, 256>>>(bkk[3], tcb[1]);
    k_matvec<<<dim3(NUM_CLASSES, 2), 256>>>(trans, (float*)d_out);
}